// round 1
// baseline (speedup 1.0000x reference)
#include <cuda_runtime.h>
#include <cstdint>

// LocalLayer: y[8192,4096] = x[8192,4096] @ W.T + b, W banded:
// output group k (16 outs) uses input window [clamp(16k-32,0,4032), +64).
// W is zero outside the band, so uniform 64-col segments are exact.

#define IN_F   4096
#define OUT_F  4096
#define NBATCH 8192

#define BROWS  128      // batch rows per CTA
#define XCOLS  112      // input-column span of 4 adjacent windows
#define XPITCH 116      // smem pitch (mult of 4, conflict-free col loads)
#define NTHR   256

// smem floats: x tile + W tile (interleaved [win][jc][out16][4])
#define XS_FLOATS (BROWS * XPITCH)           // 14848
#define WS_FLOATS (4 * 16 * 16 * 4)          // 4096
#define SMEM_BYTES ((XS_FLOATS + WS_FLOATS) * 4)

__device__ __forceinline__ unsigned long long fma2(unsigned long long a,
                                                   unsigned long long b,
                                                   unsigned long long c) {
    unsigned long long d;
    asm("fma.rn.f32x2 %0, %1, %2, %3;" : "=l"(d) : "l"(a), "l"(b), "l"(c));
    return d;
}

__device__ __forceinline__ float2 unpack2(unsigned long long v) {
    float2 r;
    asm("mov.b64 {%0, %1}, %2;" : "=f"(r.x), "=f"(r.y) : "l"(v));
    return r;
}

__device__ __forceinline__ int clampi(int v, int lo, int hi) {
    return v < lo ? lo : (v > hi ? hi : v);
}

extern "C" __global__ void __launch_bounds__(NTHR, 2)
local_layer_kernel(const float* __restrict__ x,
                   const float* __restrict__ W,
                   const float* __restrict__ b,
                   float* __restrict__ y)
{
    extern __shared__ float smem[];
    float* xs = smem;                 // [BROWS][XPITCH]
    float* ws = smem + XS_FLOATS;     // [win][jc][out16][4]

    const int rb = blockIdx.x;        // 0..63 (row block)
    const int g  = blockIdx.y;        // 0..63 (window group: windows 4g..4g+3, outs 64g..64g+63)
    const int rbase = rb * BROWS;
    const int k0 = g * 4;
    const int jb = clampi(16 * k0 - 32, 0, IN_F - XCOLS);   // x tile col base (mult of 16)

    const int tid = threadIdx.x;

    // ---- stage x tile: 128 rows x 112 cols (row-major, float4 loads/stores) ----
    #pragma unroll
    for (int i = 0; i < 14; i++) {
        int idx = tid + NTHR * i;              // 0..3583
        int row = idx / 28;
        int c4  = idx - row * 28;
        float4 v = *(const float4*)(x + (size_t)(rbase + row) * IN_F + jb + 4 * c4);
        *(float4*)(xs + row * XPITCH + 4 * c4) = v;
    }

    // ---- stage W tile: 4 windows x 16 outs x 64 cols, interleaved for mainloop ----
    #pragma unroll
    for (int i = 0; i < 4; i++) {
        int idx = tid + NTHR * i;              // 0..1023
        int win = idx >> 8;                    // 0..3
        int rem = idx & 255;
        int o   = rem >> 4;                    // 0..15
        int jc  = rem & 15;                    // 0..15 (4-col chunk)
        int j0  = clampi(16 * (k0 + win) - 32, 0, IN_F - 64);
        int go  = 64 * g + win * 16 + o;
        float4 v = *(const float4*)(W + (size_t)go * IN_F + j0 + 4 * jc);
        *(float4*)(ws + ((win * 16 + jc) * 16 + o) * 4) = v;
    }
    __syncthreads();

    // ---- mainloop: warp = (window, row-half); thread tile = 8 rows x 4 outs ----
    const int w    = tid >> 5;
    const int lane = tid & 31;
    const int win  = w & 3;          // 4 warps per window... (2 row-warps x 4 windows)
    const int wrow = w >> 2;         // 0..1 (64 rows each)
    const int tcol = lane & 3;       // 4 outs each
    const int trow = lane >> 2;      // 8 row-slots; thread rows = trow + 8*i (strided)

    const int j0w  = clampi(16 * (k0 + win) - 32, 0, IN_F - 64);
    const int woff = j0w - jb;       // in {0..48}, mult of 16

    unsigned long long acc[8][4];
    #pragma unroll
    for (int i = 0; i < 8; i++)
        #pragma unroll
        for (int o = 0; o < 4; o++) acc[i][o] = 0ull;

    const float* xbase = xs + (wrow * 64 + trow) * XPITCH + woff;
    const float* wbase = ws + (win * 16 * 16 + tcol * 4) * 4;

    #pragma unroll 4
    for (int jc = 0; jc < 16; jc++) {          // 4 columns per step
        const ulonglong2* wp = (const ulonglong2*)(wbase + jc * 64);
        ulonglong2 w0 = wp[0];
        ulonglong2 w1 = wp[1];
        ulonglong2 w2 = wp[2];
        ulonglong2 w3 = wp[3];
        const float* xp = xbase + jc * 4;
        #pragma unroll
        for (int i = 0; i < 8; i++) {
            ulonglong2 xv = *(const ulonglong2*)(xp + i * 8 * XPITCH);
            acc[i][0] = fma2(xv.x, w0.x, acc[i][0]);
            acc[i][0] = fma2(xv.y, w0.y, acc[i][0]);
            acc[i][1] = fma2(xv.x, w1.x, acc[i][1]);
            acc[i][1] = fma2(xv.y, w1.y, acc[i][1]);
            acc[i][2] = fma2(xv.x, w2.x, acc[i][2]);
            acc[i][2] = fma2(xv.y, w2.y, acc[i][2]);
            acc[i][3] = fma2(xv.x, w3.x, acc[i][3]);
            acc[i][3] = fma2(xv.y, w3.y, acc[i][3]);
        }
    }

    // ---- epilogue: reduce pairs, add bias, store float4 per row ----
    const int obase = 64 * g + win * 16 + tcol * 4;
    float4 bias = *(const float4*)(b + obase);

    #pragma unroll
    for (int i = 0; i < 8; i++) {
        int row = rbase + wrow * 64 + trow + 8 * i;
        float2 a0 = unpack2(acc[i][0]);
        float2 a1 = unpack2(acc[i][1]);
        float2 a2 = unpack2(acc[i][2]);
        float2 a3 = unpack2(acc[i][3]);
        float4 out;
        out.x = a0.x + a0.y + bias.x;
        out.y = a1.x + a1.y + bias.y;
        out.z = a2.x + a2.y + bias.z;
        out.w = a3.x + a3.y + bias.w;
        *(float4*)(y + (size_t)row * OUT_F + obase) = out;
    }
}

extern "C" void kernel_launch(void* const* d_in, const int* in_sizes, int n_in,
                              void* d_out, int out_size) {
    const float* x = (const float*)d_in[0];
    const float* W = (const float*)d_in[1];
    const float* b = (const float*)d_in[2];
    // d_in[3] = mask, unused (already baked into W at init)
    float* y = (float*)d_out;

    cudaFuncSetAttribute(local_layer_kernel,
                         cudaFuncAttributeMaxDynamicSharedMemorySize, SMEM_BYTES);

    dim3 grid(NBATCH / BROWS, OUT_F / 64);   // 64 x 64
    local_layer_kernel<<<grid, NTHR, SMEM_BYTES>>>(x, W, b, y);
}

// round 2
// speedup vs baseline: 1.0807x; 1.0807x over previous
#include <cuda_runtime.h>
#include <cstdint>

// LocalLayer: y[8192,4096] = x[8192,4096] @ W.T + b, W banded:
// output group k (16 outs) uses input window [clamp(16k-32,0,4032), +64).
// W is exactly zero outside the band, so uniform 64-col segments are exact.

#define IN_F   4096
#define OUT_F  4096
#define NBATCH 8192

#define BROWS  128      // batch rows per CTA
#define XCOLS  112      // input-column span of 4 adjacent windows
#define XPITCH 116      // x smem pitch in floats (mult of 4; 29*16B lane stride -> conflict-free)
#define YPITCH 68       // y smem pitch in floats (epilogue transpose)
#define NTHR   256

#define XS_FLOATS (BROWS * XPITCH)           // 14848
#define WS_FLOATS (4 * 16 * 64)              // 4096 (W tile [win][out][col])
#define SMEM_BYTES ((XS_FLOATS + WS_FLOATS) * 4)

__device__ __forceinline__ unsigned long long fma2(unsigned long long a,
                                                   unsigned long long b,
                                                   unsigned long long c) {
    unsigned long long d;
    asm("fma.rn.f32x2 %0, %1, %2, %3;" : "=l"(d) : "l"(a), "l"(b), "l"(c));
    return d;
}

__device__ __forceinline__ float2 unpack2(unsigned long long v) {
    float2 r;
    asm("mov.b64 {%0, %1}, %2;" : "=f"(r.x), "=f"(r.y) : "l"(v));
    return r;
}

__device__ __forceinline__ int clampi(int v, int lo, int hi) {
    return v < lo ? lo : (v > hi ? hi : v);
}

extern "C" __global__ void __launch_bounds__(NTHR, 2)
local_layer_kernel(const float* __restrict__ x,
                   const float* __restrict__ W,
                   const float* __restrict__ b,
                   float* __restrict__ y)
{
    extern __shared__ float smem[];
    float* xs = smem;                 // [BROWS][XPITCH]
    float* ws = smem + XS_FLOATS;     // [win][out16][col64]

    const int rb = blockIdx.x;        // row block (64)
    const int g  = blockIdx.y;        // window group (64): windows 4g..4g+3, outs 64g..64g+63
    const int rbase = rb * BROWS;
    const int k0 = g * 4;
    const int jb = clampi(16 * k0 - 32, 0, IN_F - XCOLS);   // x tile col base

    const int tid = threadIdx.x;

    // ---- stage x tile: 128 rows x 112 cols (coalesced LDG.128 -> STS.128) ----
    #pragma unroll
    for (int i = 0; i < 14; i++) {
        int idx = tid + NTHR * i;              // 0..3583
        int row = idx / 28;
        int c4  = idx - row * 28;
        float4 v = *(const float4*)(x + (size_t)(rbase + row) * IN_F + jb + 4 * c4);
        *(float4*)(xs + row * XPITCH + 4 * c4) = v;
    }

    // ---- stage W tile: [win][o][col] direct copy (contiguous, conflict-free) ----
    #pragma unroll
    for (int i = 0; i < 4; i++) {
        int idx = tid + NTHR * i;              // 0..1023
        int win = idx >> 8;                    // 0..3
        int o   = (idx >> 4) & 15;             // 0..15
        int jc  = idx & 15;                    // 0..15 (4-col chunk)
        int j0  = clampi(16 * (k0 + win) - 32, 0, IN_F - 64);
        int go  = 64 * g + win * 16 + o;
        float4 v = *(const float4*)(W + (size_t)go * IN_F + j0 + 4 * jc);
        *(float4*)(ws + (win * 16 + o) * 64 + 4 * jc) = v;
    }
    __syncthreads();

    // ---- mainloop: warp = (window, row-half). Lane owns rows {base+lane, base+lane+32}.
    //      acc[h][o] is f32x2: lo accumulates even-j, hi accumulates odd-j.
    const int w    = tid >> 5;
    const int lane = tid & 31;
    const int win  = w & 3;
    const int rowhalf = w >> 2;      // 0..1 (64 rows each)

    const int j0w  = clampi(16 * (k0 + win) - 32, 0, IN_F - 64);
    const int woff = j0w - jb;       // in {0..48}, mult of 16

    unsigned long long acc0[16], acc1[16];
    #pragma unroll
    for (int o = 0; o < 16; o++) { acc0[o] = 0ull; acc1[o] = 0ull; }

    const float* xp0 = xs + (rowhalf * 64 + lane) * XPITCH + woff;
    const float* xp1 = xp0 + 32 * XPITCH;
    const float* wbase = ws + win * 16 * 64;

    #pragma unroll 4
    for (int jc = 0; jc < 16; jc++) {          // 4 columns per step
        ulonglong2 xv0 = *(const ulonglong2*)(xp0 + 4 * jc);
        ulonglong2 xv1 = *(const ulonglong2*)(xp1 + 4 * jc);
        const float* wp = wbase + 4 * jc;
        #pragma unroll
        for (int o = 0; o < 16; o++) {
            ulonglong2 wv = *(const ulonglong2*)(wp + o * 64);  // broadcast: 1 wf
            acc0[o] = fma2(xv0.x, wv.x, acc0[o]);
            acc0[o] = fma2(xv0.y, wv.y, acc0[o]);
            acc1[o] = fma2(xv1.x, wv.x, acc1[o]);
            acc1[o] = fma2(xv1.y, wv.y, acc1[o]);
        }
    }

    // ---- epilogue: reduce + bias -> smem transpose -> coalesced STG ----
    __syncthreads();                 // done reading xs/ws; reuse smem as y tile
    float* ys = smem;                // [BROWS][YPITCH]

    const int obase = 64 * g + win * 16;
    float4 bv0 = *(const float4*)(b + obase);
    float4 bv1 = *(const float4*)(b + obase + 4);
    float4 bv2 = *(const float4*)(b + obase + 8);
    float4 bv3 = *(const float4*)(b + obase + 12);
    float bias[16] = {bv0.x,bv0.y,bv0.z,bv0.w, bv1.x,bv1.y,bv1.z,bv1.w,
                      bv2.x,bv2.y,bv2.z,bv2.w, bv3.x,bv3.y,bv3.z,bv3.w};

    #pragma unroll
    for (int h = 0; h < 2; h++) {
        int r = rowhalf * 64 + lane + 32 * h;
        const unsigned long long* acc = h ? acc1 : acc0;
        float out[16];
        #pragma unroll
        for (int o = 0; o < 16; o++) {
            float2 a = unpack2(acc[o]);
            out[o] = a.x + a.y + bias[o];
        }
        float* yp = ys + r * YPITCH + win * 16;
        #pragma unroll
        for (int q = 0; q < 4; q++) {
            float4 v = make_float4(out[4*q], out[4*q+1], out[4*q+2], out[4*q+3]);
            *(float4*)(yp + 4 * q) = v;
        }
    }
    __syncthreads();

    #pragma unroll
    for (int i = 0; i < 8; i++) {
        int idx = tid + NTHR * i;              // 0..2047
        int row = idx >> 4;
        int c4  = idx & 15;
        float4 v = *(const float4*)(ys + row * YPITCH + 4 * c4);
        *(float4*)(y + (size_t)(rbase + row) * OUT_F + 64 * g + 4 * c4) = v;
    }
}

extern "C" void kernel_launch(void* const* d_in, const int* in_sizes, int n_in,
                              void* d_out, int out_size) {
    const float* x = (const float*)d_in[0];
    const float* W = (const float*)d_in[1];
    const float* b = (const float*)d_in[2];
    // d_in[3] = mask, unused (already baked into W at init)
    float* y = (float*)d_out;

    cudaFuncSetAttribute(local_layer_kernel,
                         cudaFuncAttributeMaxDynamicSharedMemorySize, SMEM_BYTES);

    dim3 grid(NBATCH / BROWS, OUT_F / 64);   // 64 x 64
    local_layer_kernel<<<grid, NTHR, SMEM_BYTES>>>(x, W, b, y);
}

// round 3
// speedup vs baseline: 1.1462x; 1.0606x over previous
#include <cuda_runtime.h>
#include <cstdint>

// LocalLayer: y[8192,4096] = x[8192,4096] @ W.T + b, W banded:
// output group k (16 outs) uses input window [clamp(16k-32,0,4032), +64).
// W is exactly zero outside the band, so uniform 64-col segments are exact.

#define IN_F   4096
#define OUT_F  4096
#define NBATCH 8192

#define BROWS  128      // batch rows per CTA
#define XCOLS  112      // input-column span of 4 adjacent windows
#define XPITCH 116      // x smem pitch (floats); lane stride 29*16B -> conflict-free
#define YPITCH 68       // y smem pitch for epilogue transpose
#define NTHR   256

#define XS_FLOATS (BROWS * XPITCH)           // 14848
#define WS_FLOATS (4 * 16 * 64)              // 4096 (W tile [win][out][col])
#define SMEM_BYTES ((XS_FLOATS + WS_FLOATS) * 4)

__device__ __forceinline__ unsigned long long fma2(unsigned long long a,
                                                   unsigned long long b,
                                                   unsigned long long c) {
    unsigned long long d;
    asm("fma.rn.f32x2 %0, %1, %2, %3;" : "=l"(d) : "l"(a), "l"(b), "l"(c));
    return d;
}

__device__ __forceinline__ float2 unpack2(unsigned long long v) {
    float2 r;
    asm("mov.b64 {%0, %1}, %2;" : "=f"(r.x), "=f"(r.y) : "l"(v));
    return r;
}

__device__ __forceinline__ int clampi(int v, int lo, int hi) {
    return v < lo ? lo : (v > hi ? hi : v);
}

extern "C" __global__ void __launch_bounds__(NTHR, 2)
local_layer_kernel(const float* __restrict__ x,
                   const float* __restrict__ W,
                   const float* __restrict__ b,
                   float* __restrict__ y)
{
    extern __shared__ float smem[];
    float* xs = smem;                 // [BROWS][XPITCH]
    float* ws = smem + XS_FLOATS;     // [win][out16][col64]

    const int rb = blockIdx.x;        // row block (64)
    const int g  = blockIdx.y;        // window group (64): windows 4g..4g+3, outs 64g..64g+63
    const int rbase = rb * BROWS;
    const int k0 = g * 4;
    const int jb = clampi(16 * k0 - 32, 0, IN_F - XCOLS);   // x tile col base

    const int tid = threadIdx.x;

    // ---- stage x tile: 128 rows x 112 cols ----
    #pragma unroll
    for (int i = 0; i < 14; i++) {
        int idx = tid + NTHR * i;              // 0..3583
        int row = idx / 28;
        int c4  = idx - row * 28;
        float4 v = *(const float4*)(x + (size_t)(rbase + row) * IN_F + jb + 4 * c4);
        *(float4*)(xs + row * XPITCH + 4 * c4) = v;
    }

    // ---- stage W tile: [win][o][col] ----
    #pragma unroll
    for (int i = 0; i < 4; i++) {
        int idx = tid + NTHR * i;              // 0..1023
        int win = idx >> 8;
        int o   = (idx >> 4) & 15;
        int jc  = idx & 15;
        int j0  = clampi(16 * (k0 + win) - 32, 0, IN_F - 64);
        int go  = 64 * g + win * 16 + o;
        float4 v = *(const float4*)(W + (size_t)go * IN_F + j0 + 4 * jc);
        *(float4*)(ws + (win * 16 + o) * 64 + 4 * jc) = v;
    }
    __syncthreads();

    // ---- mainloop: warp = (window, row-half). Lane owns rows {base+lane, +32}. ----
    const int w    = tid >> 5;
    const int lane = tid & 31;
    const int win  = w & 3;
    const int rowhalf = w >> 2;

    const int j0w  = clampi(16 * (k0 + win) - 32, 0, IN_F - 64);
    const int woff = j0w - jb;

    unsigned long long acc0[16], acc1[16];
    #pragma unroll
    for (int o = 0; o < 16; o++) { acc0[o] = 0ull; acc1[o] = 0ull; }

    const float* xp0 = xs + (rowhalf * 64 + lane) * XPITCH + woff;
    const float* xp1 = xp0 + 32 * XPITCH;
    const float* wbase = ws + win * 16 * 64;

    // Software pipeline over 64 stages: stage s -> (jc = s>>2, oc = s&3).
    // wv double-buffered one stage (4 outs) ahead; xv double-buffered one jc ahead.
    ulonglong2 wv[2][4];
    ulonglong2 xv0[2], xv1[2];

    xv0[0] = *(const ulonglong2*)(xp0);
    xv1[0] = *(const ulonglong2*)(xp1);
    #pragma unroll
    for (int i = 0; i < 4; i++)
        wv[0][i] = *(const ulonglong2*)(wbase + i * 64);

    #pragma unroll
    for (int s = 0; s < 64; s++) {
        const int jc  = s >> 2;
        const int oc  = s & 3;
        const int cur = s & 1;
        const int nxt = cur ^ 1;
        const int xb  = jc & 1;

        // prefetch next stage's W chunk (compile-time offsets)
        const int s1 = (s + 1) & 63;
        const int jn = s1 >> 2;
        const int on = s1 & 3;
        #pragma unroll
        for (int i = 0; i < 4; i++)
            wv[nxt][i] = *(const ulonglong2*)(wbase + (4 * on + i) * 64 + 4 * jn);

        // prefetch next jc's x pair at the last oc of this jc
        if (oc == 3) {
            const int jx = (jc + 1) & 15;
            xv0[xb ^ 1] = *(const ulonglong2*)(xp0 + 4 * jx);
            xv1[xb ^ 1] = *(const ulonglong2*)(xp1 + 4 * jx);
        }

        const ulonglong2 a0 = xv0[xb];
        const ulonglong2 a1 = xv1[xb];
        #pragma unroll
        for (int i = 0; i < 4; i++) {
            const int o = 4 * oc + i;
            const ulonglong2 wvv = wv[cur][i];
            acc0[o] = fma2(a0.x, wvv.x, acc0[o]);
            acc1[o] = fma2(a1.x, wvv.x, acc1[o]);
            acc0[o] = fma2(a0.y, wvv.y, acc0[o]);
            acc1[o] = fma2(a1.y, wvv.y, acc1[o]);
        }
    }

    // ---- epilogue: reduce + bias -> smem transpose -> coalesced STG ----
    __syncthreads();
    float* ys = smem;                // [BROWS][YPITCH]

    const int obase = 64 * g + win * 16;
    float4 bv0 = *(const float4*)(b + obase);
    float4 bv1 = *(const float4*)(b + obase + 4);
    float4 bv2 = *(const float4*)(b + obase + 8);
    float4 bv3 = *(const float4*)(b + obase + 12);
    float bias[16] = {bv0.x,bv0.y,bv0.z,bv0.w, bv1.x,bv1.y,bv1.z,bv1.w,
                      bv2.x,bv2.y,bv2.z,bv2.w, bv3.x,bv3.y,bv3.z,bv3.w};

    #pragma unroll
    for (int h = 0; h < 2; h++) {
        int r = rowhalf * 64 + lane + 32 * h;
        const unsigned long long* acc = h ? acc1 : acc0;
        float out[16];
        #pragma unroll
        for (int o = 0; o < 16; o++) {
            float2 a = unpack2(acc[o]);
            out[o] = a.x + a.y + bias[o];
        }
        float* yp = ys + r * YPITCH + win * 16;
        #pragma unroll
        for (int q = 0; q < 4; q++) {
            float4 v = make_float4(out[4*q], out[4*q+1], out[4*q+2], out[4*q+3]);
            *(float4*)(yp + 4 * q) = v;
        }
    }
    __syncthreads();

    #pragma unroll
    for (int i = 0; i < 8; i++) {
        int idx = tid + NTHR * i;              // 0..2047
        int row = idx >> 4;
        int c4  = idx & 15;
        float4 v = *(const float4*)(ys + row * YPITCH + 4 * c4);
        *(float4*)(y + (size_t)(rbase + row) * OUT_F + 64 * g + 4 * c4) = v;
    }
}

extern "C" void kernel_launch(void* const* d_in, const int* in_sizes, int n_in,
                              void* d_out, int out_size) {
    const float* x = (const float*)d_in[0];
    const float* W = (const float*)d_in[1];
    const float* b = (const float*)d_in[2];
    // d_in[3] = mask, unused (already baked into W at init)
    float* y = (float*)d_out;

    cudaFuncSetAttribute(local_layer_kernel,
                         cudaFuncAttributeMaxDynamicSharedMemorySize, SMEM_BYTES);

    dim3 grid(NBATCH / BROWS, OUT_F / 64);   // 64 x 64
    local_layer_kernel<<<grid, NTHR, SMEM_BYTES>>>(x, W, b, y);
}

// round 4
// speedup vs baseline: 1.2475x; 1.0884x over previous
#include <cuda_runtime.h>
#include <cstdint>

// LocalLayer: y[8192,4096] = x[8192,4096] @ W.T + b, W banded:
// output group k (16 outs) uses input window [clamp(16k-32,0,4032), +64).
// W is exactly zero outside the band, so uniform 64-col segments are exact.

#define IN_F   4096
#define OUT_F  4096
#define NBATCH 8192

#define BROWS  128      // batch rows per CTA
#define XCOLS  112      // input-column span of 4 adjacent windows
#define XPITCH 116      // x smem pitch (floats); 32-lane stride 116 -> conflict-free
#define YPITCH 68       // y smem pitch for epilogue transpose
#define NTHR   256

#define XS_FLOATS (BROWS * XPITCH)           // 14848
#define WS_FLOATS (4 * 16 * 64)              // 4096 (W tile [win][out][col])
#define SMEM_BYTES ((XS_FLOATS + WS_FLOATS) * 4)

__device__ __forceinline__ unsigned long long fma2(unsigned long long a,
                                                   unsigned long long b,
                                                   unsigned long long c) {
    unsigned long long d;
    asm("fma.rn.f32x2 %0, %1, %2, %3;" : "=l"(d) : "l"(a), "l"(b), "l"(c));
    return d;
}

__device__ __forceinline__ float2 unpack2(unsigned long long v) {
    float2 r;
    asm("mov.b64 {%0, %1}, %2;" : "=f"(r.x), "=f"(r.y) : "l"(v));
    return r;
}

__device__ __forceinline__ int clampi(int v, int lo, int hi) {
    return v < lo ? lo : (v > hi ? hi : v);
}

extern "C" __global__ void __launch_bounds__(NTHR, 2)
local_layer_kernel(const float* __restrict__ x,
                   const float* __restrict__ W,
                   const float* __restrict__ b,
                   float* __restrict__ y)
{
    extern __shared__ float smem[];
    float* xs = smem;                 // [BROWS][XPITCH]
    float* ws = smem + XS_FLOATS;     // [win][out16][col64]

    const int rb = blockIdx.x;        // row block (64)
    const int g  = blockIdx.y;        // window group (64): windows 4g..4g+3, outs 64g..64g+63
    const int rbase = rb * BROWS;
    const int k0 = g * 4;
    const int jb = clampi(16 * k0 - 32, 0, IN_F - XCOLS);   // x tile col base

    const int tid = threadIdx.x;

    // ---- stage x tile: 128 rows x 112 cols ----
    #pragma unroll
    for (int i = 0; i < 14; i++) {
        int idx = tid + NTHR * i;              // 0..3583
        int row = idx / 28;
        int c4  = idx - row * 28;
        float4 v = *(const float4*)(x + (size_t)(rbase + row) * IN_F + jb + 4 * c4);
        *(float4*)(xs + row * XPITCH + 4 * c4) = v;
    }

    // ---- stage W tile: [win][o][col] ----
    #pragma unroll
    for (int i = 0; i < 4; i++) {
        int idx = tid + NTHR * i;              // 0..1023
        int win = idx >> 8;
        int o   = (idx >> 4) & 15;
        int jc  = idx & 15;
        int j0  = clampi(16 * (k0 + win) - 32, 0, IN_F - 64);
        int go  = 64 * g + win * 16 + o;
        float4 v = *(const float4*)(W + (size_t)go * IN_F + j0 + 4 * jc);
        *(float4*)(ws + (win * 16 + o) * 64 + 4 * jc) = v;
    }
    __syncthreads();

    // ---- mainloop: warp = all 128 rows x 8 outs. Lane owns rows lane+32r. ----
    const int w    = tid >> 5;
    const int lane = tid & 31;
    const int win  = w >> 1;          // 0..3
    const int ob8  = (w & 1) * 8;     // out offset within window

    const int j0w  = clampi(16 * (k0 + win) - 32, 0, IN_F - 64);
    const int woff = j0w - jb;        // {0..48}, mult of 16

    unsigned long long acc[4][8];
    #pragma unroll
    for (int r = 0; r < 4; r++)
        #pragma unroll
        for (int o = 0; o < 8; o++) acc[r][o] = 0ull;

    const float* xpb = xs + lane * XPITCH + woff;      // + r*32*XPITCH + 4*jc
    const float* wb  = ws + (win * 16 + ob8) * 64;     // + o*64 + 4*jc

    // Pipeline: 64 stages, stage s -> (jc = s>>2, oh = s&3 -> outs {2oh, 2oh+1}).
    // wv double-buffered one stage ahead (2 LDS per stage, 16 FFMA2 apart).
    // xv double-buffered by jc parity, prefetched at oh==0 of previous jc.
    ulonglong2 wv[2][2];
    ulonglong2 xv[2][4];

    #pragma unroll
    for (int r = 0; r < 4; r++)
        xv[0][r] = *(const ulonglong2*)(xpb + r * 32 * XPITCH);
    #pragma unroll
    for (int i = 0; i < 2; i++)
        wv[0][i] = *(const ulonglong2*)(wb + i * 64);

    #pragma unroll
    for (int s = 0; s < 64; s++) {
        const int jc = s >> 2;
        const int oh = s & 3;
        const int cur = s & 1;
        const int nxt = cur ^ 1;

        // prefetch next stage's W pair (compile-time offsets)
        const int s1 = (s + 1) & 63;
        const int jn = s1 >> 2;
        const int on = s1 & 3;
        #pragma unroll
        for (int i = 0; i < 2; i++)
            wv[nxt][i] = *(const ulonglong2*)(wb + (2 * on + i) * 64 + 4 * jn);

        // prefetch next jc's x rows early in this jc
        if (oh == 0) {
            const int jx = (jc + 1) & 15;
            #pragma unroll
            for (int r = 0; r < 4; r++)
                xv[(jc + 1) & 1][r] =
                    *(const ulonglong2*)(xpb + r * 32 * XPITCH + 4 * jx);
        }

        #pragma unroll
        for (int r = 0; r < 4; r++) {
            const ulonglong2 a = xv[jc & 1][r];
            #pragma unroll
            for (int i = 0; i < 2; i++) {
                const int o = 2 * oh + i;
                const ulonglong2 wvv = wv[cur][i];
                acc[r][o] = fma2(a.x, wvv.x, acc[r][o]);
                acc[r][o] = fma2(a.y, wvv.y, acc[r][o]);
            }
        }
    }

    // ---- epilogue: reduce + bias -> smem transpose -> coalesced STG ----
    __syncthreads();
    float* ys = smem;                // [BROWS][YPITCH]

    const int obase = 64 * g + win * 16 + ob8;
    float4 bv0 = *(const float4*)(b + obase);
    float4 bv1 = *(const float4*)(b + obase + 4);
    float bias[8] = {bv0.x, bv0.y, bv0.z, bv0.w, bv1.x, bv1.y, bv1.z, bv1.w};

    #pragma unroll
    for (int r = 0; r < 4; r++) {
        float out[8];
        #pragma unroll
        for (int o = 0; o < 8; o++) {
            float2 a = unpack2(acc[r][o]);
            out[o] = a.x + a.y + bias[o];
        }
        float* yp = ys + (lane + 32 * r) * YPITCH + win * 16 + ob8;
        *(float4*)(yp)     = make_float4(out[0], out[1], out[2], out[3]);
        *(float4*)(yp + 4) = make_float4(out[4], out[5], out[6], out[7]);
    }
    __syncthreads();

    #pragma unroll
    for (int i = 0; i < 8; i++) {
        int idx = tid + NTHR * i;              // 0..2047
        int row = idx >> 4;
        int c4  = idx & 15;
        float4 v = *(const float4*)(ys + row * YPITCH + 4 * c4);
        *(float4*)(y + (size_t)(rbase + row) * OUT_F + 64 * g + 4 * c4) = v;
    }
}

extern "C" void kernel_launch(void* const* d_in, const int* in_sizes, int n_in,
                              void* d_out, int out_size) {
    const float* x = (const float*)d_in[0];
    const float* W = (const float*)d_in[1];
    const float* b = (const float*)d_in[2];
    // d_in[3] = mask, unused (already baked into W at init)
    float* y = (float*)d_out;

    cudaFuncSetAttribute(local_layer_kernel,
                         cudaFuncAttributeMaxDynamicSharedMemorySize, SMEM_BYTES);

    dim3 grid(NBATCH / BROWS, OUT_F / 64);   // 64 x 64
    local_layer_kernel<<<grid, NTHR, SMEM_BYTES>>>(x, W, b, y);
}